// round 10
// baseline (speedup 1.0000x reference)
#include <cuda_runtime.h>
#include <math.h>
#include <float.h>

// Problem constants (fixed by the dataset)
#define BB 1024
#define LL 81
#define HH 8
#define DD 64
#define UU 10
#define NSAMP 41
#define WS 9
#define QSTR 68
#define KSTR 68

#define NTHREADS 256

// Shared memory layout (floats) — bias padded to 292 to keep csum 8B-aligned:
//   Qs 5508 | Ks 5508 | Vs 5184 | bias 292 | pmx 924 | psm 924 | csum 128
//   topi 16 ints | rank_of 81 ints
#define BIAS_PAD 292
#define SM_FLOATS (81*QSTR + 81*KSTR + 81*DD + BIAS_PAD + 924 + 924 + 128)
#define SM_BYTES  (SM_FLOATS*4 + (16 + 81)*4)

__device__ __forceinline__ unsigned long long ffma2(unsigned long long a,
                                                    unsigned long long b,
                                                    unsigned long long c) {
    unsigned long long d;
    asm("fma.rn.f32x2 %0, %1, %2, %3;" : "=l"(d) : "l"(a), "l"(b), "l"(c));
    return d;
}
__device__ __forceinline__ float f2sum(unsigned long long a) {
    return __uint_as_float((unsigned)(a & 0xffffffffull)) +
           __uint_as_float((unsigned)(a >> 32));
}

__global__ __launch_bounds__(NTHREADS, 3)
void prob_attn_kernel(const float* __restrict__ q_in,
                      const float* __restrict__ k_in,
                      const float* __restrict__ v_in,
                      const float* __restrict__ bias_in,
                      float* __restrict__ out_ctx,
                      float* __restrict__ out_attn)
{
    extern __shared__ float sm[];
    float* Qs    = sm;
    float* Ks    = Qs + 81*QSTR;
    float* Vs    = Ks + 81*KSTR;
    float* biass = Vs + 81*DD;
    float* pmx   = biass + BIAS_PAD;
    float* psm   = pmx + 924;
    float* csum  = psm + 924;          // float offset 18340: even -> 8B aligned
    int*   topi  = (int*)(csum + 128);
    int*   rank_of = topi + 16;

    const int tid  = threadIdx.x;
    const int warp = tid >> 5;
    const int lane = tid & 31;

    const int blk = blockIdx.x;
    const int b = blk >> 3;
    const int h = blk & 7;

    const size_t base = ((size_t)b * LL * HH + h) * DD;
    const float* qb = q_in + base;
    const float* kb = k_in + base;
    const float* vb = v_in + base;

    // ---- Phase A: load tiles (coalesced float4), bias, init rank map ----
    for (int idx = tid; idx < LL * 16; idx += NTHREADS) {
        int row = idx >> 4;
        int vec = idx & 15;
        size_t goff = (size_t)row * (HH * DD) + vec * 4;
        float4 qv = *(const float4*)(qb + goff);
        float4 kv = *(const float4*)(kb + goff);
        float4 vv = *(const float4*)(vb + goff);
        *(float4*)(Qs + row*QSTR + vec*4) = qv;
        *(float4*)(Ks + row*KSTR + vec*4) = kv;
        *(float4*)(Vs + row*DD   + vec*4) = vv;
    }
    for (int i = tid; i < 289; i += NTHREADS) biass[i] = bias_in[i];
    if (tid < LL) rank_of[tid] = -1;
    __syncthreads();

    // ---- Phase B: sampled scores, 4q x 4s per thread, packed f32x2 FMA.
    //      q rows interleaved stride 21; s interleaved stride 11.
    if (tid < 231) {
        const int st = tid / 21;        // 0..10
        const int qt = tid - st * 21;   // 0..20

        const float* Qr[4];
        const float* Kr[4];
        #pragma unroll
        for (int i = 0; i < 4; i++) {
            int q = qt + 21 * i; if (q > 80) q = 80;
            Qr[i] = Qs + q * QSTR;
        }
        #pragma unroll
        for (int j = 0; j < 4; j++) {
            int s = st + 11 * j; if (s > 40) s = 40;
            Kr[j] = Ks + (2 * s) * KSTR;
        }

        unsigned long long acc2[4][4];
        #pragma unroll
        for (int i = 0; i < 4; i++)
            #pragma unroll
            for (int j = 0; j < 4; j++) acc2[i][j] = 0ull;

        #pragma unroll 2
        for (int d = 0; d < DD; d += 4) {
            ulonglong2 qv[4], kv[4];
            #pragma unroll
            for (int i = 0; i < 4; i++) qv[i] = *(const ulonglong2*)(Qr[i] + d);
            #pragma unroll
            for (int j = 0; j < 4; j++) kv[j] = *(const ulonglong2*)(Kr[j] + d);
            #pragma unroll
            for (int i = 0; i < 4; i++)
                #pragma unroll
                for (int j = 0; j < 4; j++) {
                    acc2[i][j] = ffma2(qv[i].x, kv[j].x, acc2[i][j]);
                    acc2[i][j] = ffma2(qv[i].y, kv[j].y, acc2[i][j]);
                }
        }

        #pragma unroll
        for (int i = 0; i < 4; i++) {
            int q = qt + 21 * i;
            if (q < LL) {
                float mx = -FLT_MAX, smv = 0.0f;
                #pragma unroll
                for (int j = 0; j < 4; j++) {
                    if (st + 11 * j < NSAMP) {
                        float v = f2sum(acc2[i][j]);
                        mx = fmaxf(mx, v);
                        smv += v;
                    }
                }
                pmx[st * 84 + q] = mx;
                psm[st * 84 + q] = smv;
            }
        }
    }
    __syncthreads();

    // ---- Phase C (warp 0): folded M-reduction + top-10.
    //      Warps 5-6 concurrently: cumsum chunk sums (float2). ----
    if (warp == 0) {
        float m0, m1, m2 = -FLT_MAX;
        {
            float mx = -FLT_MAX, smv = 0.0f;
            #pragma unroll
            for (int st = 0; st < 11; st++) {
                mx = fmaxf(mx, pmx[st * 84 + lane]);
                smv += psm[st * 84 + lane];
            }
            m0 = mx - smv * (1.0f / 81.0f);
        }
        {
            float mx = -FLT_MAX, smv = 0.0f;
            #pragma unroll
            for (int st = 0; st < 11; st++) {
                mx = fmaxf(mx, pmx[st * 84 + lane + 32]);
                smv += psm[st * 84 + lane + 32];
            }
            m1 = mx - smv * (1.0f / 81.0f);
        }
        if (lane + 64 < LL) {
            float mx = -FLT_MAX, smv = 0.0f;
            #pragma unroll
            for (int st = 0; st < 11; st++) {
                mx = fmaxf(mx, pmx[st * 84 + lane + 64]);
                smv += psm[st * 84 + lane + 64];
            }
            m2 = mx - smv * (1.0f / 81.0f);
        }

        #pragma unroll
        for (int r = 0; r < UU; r++) {
            float bv = m0; int bi = lane;
            if (m1 > bv) { bv = m1; bi = lane + 32; }
            if (m2 > bv) { bv = m2; bi = lane + 64; }
            #pragma unroll
            for (int o = 16; o > 0; o >>= 1) {
                float ov = __shfl_xor_sync(0xffffffffu, bv, o);
                int   oi = __shfl_xor_sync(0xffffffffu, bi, o);
                if (ov > bv || (ov == bv && oi < bi)) { bv = ov; bi = oi; }
            }
            if (lane == 0) { topi[r] = bi; rank_of[bi] = r; }
            if (bi == lane)           m0 = -FLT_MAX;
            else if (bi == lane + 32) m1 = -FLT_MAX;
            else if (bi == lane + 64) m2 = -FLT_MAX;
        }
    } else if (warp == 5 || warp == 6) {
        const int c = warp - 5;          // chunk 0 or 1
        const int l0 = c * 27;
        float2 s = make_float2(0.0f, 0.0f);
        #pragma unroll 9
        for (int l = l0; l < l0 + 27; l++) {
            float2 v = *(const float2*)(Vs + l * DD + 2 * lane);
            s.x += v.x; s.y += v.y;
        }
        *(float2*)(csum + c * 64 + 2 * lane) = s;
    }
    __syncthreads();

    // ---- Phase D (warps 0-4): 2 rows per warp (scores+softmax+PV+direct STG).
    //      Warps 5-7 concurrently: cumsum + store of the 71 non-selected rows. ----
    const float scale = 0.125f;
    if (warp < 5) {
        const int r0 = 2 * warp, r1 = r0 + 1;
        const int qi0 = topi[r0], qi1 = topi[r1];
        const float* q0p = Qs + qi0 * QSTR;
        const float* q1p = Qs + qi1 * QSTR;

        float sc[2][3];
        #pragma unroll
        for (int t = 0; t < 3; t++) {
            int k = lane + t * 32;
            const float* kr = Ks + (k < LL ? k : LL - 1) * KSTR;
            unsigned long long a0 = 0ull, a1 = 0ull;
            #pragma unroll
            for (int d = 0; d < DD; d += 4) {
                ulonglong2 kv = *(const ulonglong2*)(kr + d);
                ulonglong2 qa = *(const ulonglong2*)(q0p + d);
                ulonglong2 qc = *(const ulonglong2*)(q1p + d);
                a0 = ffma2(qa.x, kv.x, a0);
                a0 = ffma2(qa.y, kv.y, a0);
                a1 = ffma2(qc.x, kv.x, a1);
                a1 = ffma2(qc.y, kv.y, a1);
            }
            sc[0][t] = f2sum(a0);
            sc[1][t] = f2sum(a1);
        }

        #pragma unroll
        for (int p = 0; p < 2; p++) {
            const int r = r0 + p;
            const int ri = r / WS, rj = r % WS;   // bias row indexed by RANK (ref quirk)
            float mx = -FLT_MAX;
            #pragma unroll
            for (int t = 0; t < 3; t++) {
                int k = lane + t * 32;
                if (k < LL) {
                    int ki = k / WS, kj = k - ki * WS;
                    int bidx = (ri - ki + (WS - 1)) * (2 * WS - 1) + (rj - kj + (WS - 1));
                    sc[p][t] = (sc[p][t] + biass[bidx]) * scale;
                } else {
                    sc[p][t] = -FLT_MAX;
                }
                mx = fmaxf(mx, sc[p][t]);
            }
            #pragma unroll
            for (int o = 16; o > 0; o >>= 1)
                mx = fmaxf(mx, __shfl_xor_sync(0xffffffffu, mx, o));

            float sum = 0.0f;
            #pragma unroll
            for (int t = 0; t < 3; t++) {
                int k = lane + t * 32;
                sc[p][t] = (k < LL) ? __expf(sc[p][t] - mx) : 0.0f;
                sum += sc[p][t];
            }
            #pragma unroll
            for (int o = 16; o > 0; o >>= 1)
                sum += __shfl_xor_sync(0xffffffffu, sum, o);
            const float inv = 1.0f / sum;

            #pragma unroll
            for (int t = 0; t < 3; t++) sc[p][t] *= inv;

            if (out_attn) {
                float* ao = out_attn + (((size_t)b * HH + h) * UU + r) * LL;
                #pragma unroll
                for (int t = 0; t < 3; t++) {
                    int k = lane + t * 32;
                    if (k < LL) ao[k] = sc[p][t];
                }
            }
        }

        // PV for both rows (float2 V reads; shfl lane compile-time), direct STG.
        float2 pa0 = make_float2(0.f, 0.f), pa1 = make_float2(0.f, 0.f);
        #pragma unroll
        for (int k = 0; k < LL; k++) {
            float2 v = *(const float2*)(Vs + k * DD + 2 * lane);
            const int t = k >> 5, sl = k & 31;
            float w0 = __shfl_sync(0xffffffffu, sc[0][t], sl);
            float w1 = __shfl_sync(0xffffffffu, sc[1][t], sl);
            pa0.x += w0 * v.x; pa0.y += w0 * v.y;
            pa1.x += w1 * v.x; pa1.y += w1 * v.y;
        }
        *(float2*)(out_ctx + base + (size_t)qi0 * (HH * DD) + 2 * lane) = pa0;
        *(float2*)(out_ctx + base + (size_t)qi1 * (HH * DD) + 2 * lane) = pa1;
    } else {
        // warps 5,6,7 -> chunks 0,1,2: cumsum + store non-selected rows (float2)
        const int c = warp - 5;
        float2 acc = make_float2(0.0f, 0.0f);
        if (c > 0) { float2 t = *(const float2*)(csum + 2 * lane);      acc.x += t.x; acc.y += t.y; }
        if (c > 1) { float2 t = *(const float2*)(csum + 64 + 2 * lane); acc.x += t.x; acc.y += t.y; }
        float* ob = out_ctx + base + 2 * lane;
        const int l0 = c * 27;
        for (int l = l0; l < l0 + 27; l++) {
            float2 v = *(const float2*)(Vs + l * DD + 2 * lane);
            acc.x += v.x; acc.y += v.y;
            if (rank_of[l] < 0) {
                *(float2*)(ob + (size_t)l * (HH * DD)) = acc;
            }
        }
    }
}

extern "C" void kernel_launch(void* const* d_in, const int* in_sizes, int n_in,
                              void* d_out, int out_size)
{
    const float* q    = (const float*)d_in[0];
    const float* k    = (const float*)d_in[1];
    const float* v    = (const float*)d_in[2];
    const float* bias = (const float*)d_in[3];
    float* out = (float*)d_out;

    const long long ctx_elems  = (long long)BB * LL * HH * DD;
    const long long attn_elems = (long long)BB * HH * UU * LL;
    float* attn_out = ((long long)out_size >= ctx_elems + attn_elems)
                        ? out + ctx_elems : (float*)0;

    cudaFuncSetAttribute(prob_attn_kernel,
                         cudaFuncAttributeMaxDynamicSharedMemorySize, SM_BYTES);
    prob_attn_kernel<<<BB * HH, NTHREADS, SM_BYTES>>>(q, k, v, bias, out, attn_out);
}

// round 11
// speedup vs baseline: 1.2619x; 1.2619x over previous
#include <cuda_runtime.h>
#include <math.h>
#include <float.h>

// Problem constants (fixed by the dataset)
#define BB 1024
#define LL 81
#define HH 8
#define DD 64
#define UU 10
#define NSAMP 41
#define WS 9
#define QSTR 68
#define KSTR 68

#define NTHREADS 256

// Shared memory layout (floats) — bias padded to 292 to keep csum 8B-aligned:
//   Qs 5508 | Ks 5508 | Vs 5184 | bias 292 | pmx 924 | psm 924 | csum 128
//   topi 16 ints | rank_of 81 ints
#define BIAS_PAD 292
#define SM_FLOATS (81*QSTR + 81*KSTR + 81*DD + BIAS_PAD + 924 + 924 + 128)
#define SM_BYTES  (SM_FLOATS*4 + (16 + 81)*4)

__device__ __forceinline__ unsigned long long ffma2(unsigned long long a,
                                                    unsigned long long b,
                                                    unsigned long long c) {
    unsigned long long d;
    asm("fma.rn.f32x2 %0, %1, %2, %3;" : "=l"(d) : "l"(a), "l"(b), "l"(c));
    return d;
}
__device__ __forceinline__ float f2sum(unsigned long long a) {
    return __uint_as_float((unsigned)(a & 0xffffffffull)) +
           __uint_as_float((unsigned)(a >> 32));
}

__global__ __launch_bounds__(NTHREADS, 3)
void prob_attn_kernel(const float* __restrict__ q_in,
                      const float* __restrict__ k_in,
                      const float* __restrict__ v_in,
                      const float* __restrict__ bias_in,
                      float* __restrict__ out_ctx,
                      float* __restrict__ out_attn)
{
    extern __shared__ float sm[];
    float* Qs    = sm;
    float* Ks    = Qs + 81*QSTR;
    float* Vs    = Ks + 81*KSTR;
    float* biass = Vs + 81*DD;
    float* pmx   = biass + BIAS_PAD;
    float* psm   = pmx + 924;
    float* csum  = psm + 924;          // float offset even -> 8B aligned
    int*   topi  = (int*)(csum + 128);
    int*   rank_of = topi + 16;

    const int tid  = threadIdx.x;
    const int warp = tid >> 5;
    const int lane = tid & 31;

    const int blk = blockIdx.x;
    const int b = blk >> 3;
    const int h = blk & 7;

    const size_t base = ((size_t)b * LL * HH + h) * DD;
    const float* qb = q_in + base;
    const float* kb = k_in + base;
    const float* vb = v_in + base;

    // ---- Phase A: load tiles (coalesced float4), bias, init rank map ----
    for (int idx = tid; idx < LL * 16; idx += NTHREADS) {
        int row = idx >> 4;
        int vec = idx & 15;
        size_t goff = (size_t)row * (HH * DD) + vec * 4;
        float4 qv = *(const float4*)(qb + goff);
        float4 kv = *(const float4*)(kb + goff);
        float4 vv = *(const float4*)(vb + goff);
        *(float4*)(Qs + row*QSTR + vec*4) = qv;
        *(float4*)(Ks + row*KSTR + vec*4) = kv;
        *(float4*)(Vs + row*DD   + vec*4) = vv;
    }
    for (int i = tid; i < 289; i += NTHREADS) biass[i] = bias_in[i];
    if (tid < LL) rank_of[tid] = -1;
    __syncthreads();

    // ---- Phase B: sampled scores, 4q x 4s per thread, packed f32x2 FMA.
    //      q rows interleaved stride 21; s interleaved stride 11.
    if (tid < 231) {
        const int st = tid / 21;        // 0..10
        const int qt = tid - st * 21;   // 0..20

        const float* Qr[4];
        const float* Kr[4];
        #pragma unroll
        for (int i = 0; i < 4; i++) {
            int q = qt + 21 * i; if (q > 80) q = 80;
            Qr[i] = Qs + q * QSTR;
        }
        #pragma unroll
        for (int j = 0; j < 4; j++) {
            int s = st + 11 * j; if (s > 40) s = 40;
            Kr[j] = Ks + (2 * s) * KSTR;
        }

        unsigned long long acc2[4][4];
        #pragma unroll
        for (int i = 0; i < 4; i++)
            #pragma unroll
            for (int j = 0; j < 4; j++) acc2[i][j] = 0ull;

        #pragma unroll 2
        for (int d = 0; d < DD; d += 4) {
            ulonglong2 qv[4], kv[4];
            #pragma unroll
            for (int i = 0; i < 4; i++) qv[i] = *(const ulonglong2*)(Qr[i] + d);
            #pragma unroll
            for (int j = 0; j < 4; j++) kv[j] = *(const ulonglong2*)(Kr[j] + d);
            #pragma unroll
            for (int i = 0; i < 4; i++)
                #pragma unroll
                for (int j = 0; j < 4; j++) {
                    acc2[i][j] = ffma2(qv[i].x, kv[j].x, acc2[i][j]);
                    acc2[i][j] = ffma2(qv[i].y, kv[j].y, acc2[i][j]);
                }
        }

        #pragma unroll
        for (int i = 0; i < 4; i++) {
            int q = qt + 21 * i;
            if (q < LL) {
                float mx = -FLT_MAX, smv = 0.0f;
                #pragma unroll
                for (int j = 0; j < 4; j++) {
                    if (st + 11 * j < NSAMP) {
                        float v = f2sum(acc2[i][j]);
                        mx = fmaxf(mx, v);
                        smv += v;
                    }
                }
                pmx[st * 84 + q] = mx;
                psm[st * 84 + q] = smv;
            }
        }
    }
    __syncthreads();

    // ---- Phase C (warp 0): folded M-reduction + top-10.
    //      Warps 5-6 concurrently: cumsum chunk sums (float2). ----
    if (warp == 0) {
        float m0, m1, m2 = -FLT_MAX;
        {
            float mx = -FLT_MAX, smv = 0.0f;
            #pragma unroll
            for (int st = 0; st < 11; st++) {
                mx = fmaxf(mx, pmx[st * 84 + lane]);
                smv += psm[st * 84 + lane];
            }
            m0 = mx - smv * (1.0f / 81.0f);
        }
        {
            float mx = -FLT_MAX, smv = 0.0f;
            #pragma unroll
            for (int st = 0; st < 11; st++) {
                mx = fmaxf(mx, pmx[st * 84 + lane + 32]);
                smv += psm[st * 84 + lane + 32];
            }
            m1 = mx - smv * (1.0f / 81.0f);
        }
        if (lane + 64 < LL) {
            float mx = -FLT_MAX, smv = 0.0f;
            #pragma unroll
            for (int st = 0; st < 11; st++) {
                mx = fmaxf(mx, pmx[st * 84 + lane + 64]);
                smv += psm[st * 84 + lane + 64];
            }
            m2 = mx - smv * (1.0f / 81.0f);
        }

        #pragma unroll
        for (int r = 0; r < UU; r++) {
            float bv = m0; int bi = lane;
            if (m1 > bv) { bv = m1; bi = lane + 32; }
            if (m2 > bv) { bv = m2; bi = lane + 64; }
            #pragma unroll
            for (int o = 16; o > 0; o >>= 1) {
                float ov = __shfl_xor_sync(0xffffffffu, bv, o);
                int   oi = __shfl_xor_sync(0xffffffffu, bi, o);
                if (ov > bv || (ov == bv && oi < bi)) { bv = ov; bi = oi; }
            }
            if (lane == 0) { topi[r] = bi; rank_of[bi] = r; }
            if (bi == lane)           m0 = -FLT_MAX;
            else if (bi == lane + 32) m1 = -FLT_MAX;
            else if (bi == lane + 64) m2 = -FLT_MAX;
        }
    } else if (warp == 5 || warp == 6) {
        const int c = warp - 5;          // chunk 0 or 1
        const int l0 = c * 27;
        float2 s = make_float2(0.0f, 0.0f);
        for (int l = l0; l < l0 + 27; l++) {
            float2 v = *(const float2*)(Vs + l * DD + 2 * lane);
            s.x += v.x; s.y += v.y;
        }
        *(float2*)(csum + c * 64 + 2 * lane) = s;
    }
    __syncthreads();

    // ---- Phase D (warps 0-4): 2 rows per warp (scores+softmax+PV+direct STG).
    //      Warps 5-7 concurrently: cumsum + store of the 71 non-selected rows. ----
    const float scale = 0.125f;
    if (warp < 5) {
        const int r0 = 2 * warp, r1 = r0 + 1;
        const int qi0 = topi[r0], qi1 = topi[r1];
        const float* q0p = Qs + qi0 * QSTR;
        const float* q1p = Qs + qi1 * QSTR;

        float sc[2][3];
        #pragma unroll
        for (int t = 0; t < 3; t++) {
            int k = lane + t * 32;
            const float* kr = Ks + (k < LL ? k : LL - 1) * KSTR;
            unsigned long long a0 = 0ull, a1 = 0ull;
            #pragma unroll 4
            for (int d = 0; d < DD; d += 4) {
                ulonglong2 kv = *(const ulonglong2*)(kr + d);
                ulonglong2 qa = *(const ulonglong2*)(q0p + d);
                ulonglong2 qc = *(const ulonglong2*)(q1p + d);
                a0 = ffma2(qa.x, kv.x, a0);
                a0 = ffma2(qa.y, kv.y, a0);
                a1 = ffma2(qc.x, kv.x, a1);
                a1 = ffma2(qc.y, kv.y, a1);
            }
            sc[0][t] = f2sum(a0);
            sc[1][t] = f2sum(a1);
        }

        #pragma unroll
        for (int p = 0; p < 2; p++) {
            const int r = r0 + p;
            const int ri = r / WS, rj = r % WS;   // bias row indexed by RANK (ref quirk)
            float mx = -FLT_MAX;
            #pragma unroll
            for (int t = 0; t < 3; t++) {
                int k = lane + t * 32;
                if (k < LL) {
                    int ki = k / WS, kj = k - ki * WS;
                    int bidx = (ri - ki + (WS - 1)) * (2 * WS - 1) + (rj - kj + (WS - 1));
                    sc[p][t] = (sc[p][t] + biass[bidx]) * scale;
                } else {
                    sc[p][t] = -FLT_MAX;
                }
                mx = fmaxf(mx, sc[p][t]);
            }
            #pragma unroll
            for (int o = 16; o > 0; o >>= 1)
                mx = fmaxf(mx, __shfl_xor_sync(0xffffffffu, mx, o));

            float sum = 0.0f;
            #pragma unroll
            for (int t = 0; t < 3; t++) {
                int k = lane + t * 32;
                sc[p][t] = (k < LL) ? __expf(sc[p][t] - mx) : 0.0f;
                sum += sc[p][t];
            }
            #pragma unroll
            for (int o = 16; o > 0; o >>= 1)
                sum += __shfl_xor_sync(0xffffffffu, sum, o);
            const float inv = 1.0f / sum;

            #pragma unroll
            for (int t = 0; t < 3; t++) sc[p][t] *= inv;

            if (out_attn) {
                float* ao = out_attn + (((size_t)b * HH + h) * UU + r) * LL;
                #pragma unroll
                for (int t = 0; t < 3; t++) {
                    int k = lane + t * 32;
                    if (k < LL) ao[k] = sc[p][t];
                }
            }
        }

        // PV for both rows: outer t unrolled (compile-time sc index), inner
        // sl loop ROLLED to keep the code footprint inside the I$.
        float2 pa0 = make_float2(0.f, 0.f), pa1 = make_float2(0.f, 0.f);
        #pragma unroll
        for (int t = 0; t < 3; t++) {
            const int kmax = (t == 2) ? (LL - 64) : 32;
            const float* vbase = Vs + t * 32 * DD + 2 * lane;
            for (int sl = 0; sl < kmax; sl++) {
                float2 v = *(const float2*)(vbase + sl * DD);
                float w0 = __shfl_sync(0xffffffffu, sc[0][t], sl);
                float w1 = __shfl_sync(0xffffffffu, sc[1][t], sl);
                pa0.x += w0 * v.x; pa0.y += w0 * v.y;
                pa1.x += w1 * v.x; pa1.y += w1 * v.y;
            }
        }
        *(float2*)(out_ctx + base + (size_t)qi0 * (HH * DD) + 2 * lane) = pa0;
        *(float2*)(out_ctx + base + (size_t)qi1 * (HH * DD) + 2 * lane) = pa1;
    } else {
        // warps 5,6,7 -> chunks 0,1,2: cumsum + store non-selected rows (float2)
        const int c = warp - 5;
        float2 acc = make_float2(0.0f, 0.0f);
        if (c > 0) { float2 t = *(const float2*)(csum + 2 * lane);      acc.x += t.x; acc.y += t.y; }
        if (c > 1) { float2 t = *(const float2*)(csum + 64 + 2 * lane); acc.x += t.x; acc.y += t.y; }
        float* ob = out_ctx + base + 2 * lane;
        const int l0 = c * 27;
        for (int l = l0; l < l0 + 27; l++) {
            float2 v = *(const float2*)(Vs + l * DD + 2 * lane);
            acc.x += v.x; acc.y += v.y;
            if (rank_of[l] < 0) {
                *(float2*)(ob + (size_t)l * (HH * DD)) = acc;
            }
        }
    }
}

extern "C" void kernel_launch(void* const* d_in, const int* in_sizes, int n_in,
                              void* d_out, int out_size)
{
    const float* q    = (const float*)d_in[0];
    const float* k    = (const float*)d_in[1];
    const float* v    = (const float*)d_in[2];
    const float* bias = (const float*)d_in[3];
    float* out = (float*)d_out;

    const long long ctx_elems  = (long long)BB * LL * HH * DD;
    const long long attn_elems = (long long)BB * HH * UU * LL;
    float* attn_out = ((long long)out_size >= ctx_elems + attn_elems)
                        ? out + ctx_elems : (float*)0;

    cudaFuncSetAttribute(prob_attn_kernel,
                         cudaFuncAttributeMaxDynamicSharedMemorySize, SM_BYTES);
    prob_attn_kernel<<<BB * HH, NTHREADS, SM_BYTES>>>(q, k, v, bias, out, attn_out);
}